// round 4
// baseline (speedup 1.0000x reference)
#include <cuda_runtime.h>
#include <cuda_bf16.h>

#define S_LEN 2048
#define B_SZ  16
#define H_DIM 1024

__device__ float g_energy[B_SZ * H_DIM];

// ---------------- packed f32x2 helpers (sm_103a) ----------------
__device__ __forceinline__ unsigned long long pk2(float a, float b) {
    unsigned long long r;
    asm("mov.b64 %0, {%1,%2};" : "=l"(r) : "f"(a), "f"(b));
    return r;
}
__device__ __forceinline__ void fma2(unsigned long long& d,
                                     unsigned long long a,
                                     unsigned long long b) {
    asm("fma.rn.f32x2 %0, %1, %2, %0;" : "+l"(d) : "l"(a), "l"(b));
}
__device__ __forceinline__ float upk_sum(unsigned long long v) {
    float x, y;
    asm("mov.b64 {%0,%1}, %2;" : "=f"(x), "=f"(y) : "l"(v));
    return x + y;
}

// ---------------------------------------------------------------------------
// Kernel 1 v4: energy[b][h] = sum_j state[b][j]*W[h][j] + bias[h]
// One warp owns a (2 h-rows x 8 batches) tile:
//   - W read redundancy 16x -> 2x (two b-octets share a row pair via L1/L2)
//   - each state float4 load feeds 4 packed f32x2 FMAs
//   - 32 independent accumulator chains per warp (ILP)
// 1024 warp-tasks = 512 row-pairs x 2 octets; 256 blocks x 128 threads.
// ---------------------------------------------------------------------------
__global__ void __launch_bounds__(128)
energy_kernel(const float* __restrict__ lds,
              const float* __restrict__ W,
              const float* __restrict__ bias)
{
    const int warp = threadIdx.x >> 5;
    const int lane = threadIdx.x & 31;
    const int task = blockIdx.x * 4 + warp;    // 0..1023
    const int h0   = (task >> 1) * 2;          // row pair base
    const int ob   = (task & 1) * 8;           // batch octet base

    const float4* W4 = reinterpret_cast<const float4*>(W);
    const float4* st = reinterpret_cast<const float4*>(lds);   // [B][H/4]

    unsigned long long acc[2][8];
    #pragma unroll
    for (int r = 0; r < 2; ++r)
        #pragma unroll
        for (int b = 0; b < 8; ++b)
            acc[r][b] = 0ull;   // packed (0.f, 0.f)

    #pragma unroll
    for (int i = 0; i < 8; ++i) {
        const int idx = lane + i * 32;
        const float4 w0 = W4[(size_t)h0 * (H_DIM / 4) + idx];
        const float4 w1 = W4[(size_t)(h0 + 1) * (H_DIM / 4) + idx];
        const unsigned long long w0lo = pk2(w0.x, w0.y), w0hi = pk2(w0.z, w0.w);
        const unsigned long long w1lo = pk2(w1.x, w1.y), w1hi = pk2(w1.z, w1.w);
        #pragma unroll
        for (int b = 0; b < 8; ++b) {
            const float4 s = st[(size_t)(ob + b) * (H_DIM / 4) + idx];
            const unsigned long long slo = pk2(s.x, s.y), shi = pk2(s.z, s.w);
            fma2(acc[0][b], w0lo, slo);
            fma2(acc[0][b], w0hi, shi);
            fma2(acc[1][b], w1lo, slo);
            fma2(acc[1][b], w1hi, shi);
        }
    }

    #pragma unroll
    for (int r = 0; r < 2; ++r) {
        const float bh = bias[h0 + r];
        #pragma unroll
        for (int b = 0; b < 8; ++b) {
            float v = upk_sum(acc[r][b]);
            #pragma unroll
            for (int off = 16; off > 0; off >>= 1)
                v += __shfl_xor_sync(0xFFFFFFFF, v, off);
            if (lane == 0)
                g_energy[(size_t)(ob + b) * H_DIM + h0 + r] = v + bh;
        }
    }
}

// ---------------------------------------------------------------------------
// Kernel 2: scores[s][b] = sum_h enc[s][b][h] * energy[b][h]
// One block per (b, 8-row s-chunk): energy row in registers, reused 8x.
// (Measured near LTS cap already — unchanged from R3.)
// ---------------------------------------------------------------------------
#define VPS 8
__global__ void __launch_bounds__(128, 8)
score_kernel(const float* __restrict__ enc, float* __restrict__ out)
{
    const int b  = blockIdx.x & (B_SZ - 1);
    const int s0 = (blockIdx.x >> 4) * VPS;
    const int t  = threadIdx.x;

    const float4* e4 = reinterpret_cast<const float4*>(enc);
    const float4* g4 = reinterpret_cast<const float4*>(g_energy);

    const float4 g0 = g4[b * (H_DIM / 4) + t];
    const float4 g1 = g4[b * (H_DIM / 4) + 128 + t];

    float acc[VPS];
    #pragma unroll
    for (int i = 0; i < VPS; ++i) {
        const size_t row = ((size_t)(s0 + i) * B_SZ + b) * (H_DIM / 4);
        const float4 a0 = e4[row + t];
        const float4 a1 = e4[row + 128 + t];
        acc[i] = a0.x * g0.x + a0.y * g0.y + a0.z * g0.z + a0.w * g0.w
               + a1.x * g1.x + a1.y * g1.y + a1.z * g1.z + a1.w * g1.w;
    }

    #pragma unroll
    for (int i = 0; i < VPS; ++i)
        #pragma unroll
        for (int off = 16; off > 0; off >>= 1)
            acc[i] += __shfl_xor_sync(0xFFFFFFFF, acc[i], off);

    __shared__ float red[4][VPS];
    const int warp = t >> 5;
    const int lane = t & 31;
    if (lane == 0) {
        #pragma unroll
        for (int i = 0; i < VPS; ++i)
            red[warp][i] = acc[i];
    }
    __syncthreads();
    if (t < VPS)
        out[(size_t)(s0 + t) * B_SZ + b] =
            red[0][t] + red[1][t] + red[2][t] + red[3][t];
}

// ---------------------------------------------------------------------------
// Kernel 3: softmax over S per batch column b, in place on d_out.
// ---------------------------------------------------------------------------
__global__ void softmax_kernel(float* __restrict__ out)
{
    const int b = blockIdx.x;
    const int t = threadIdx.x;
    const int VPT = S_LEN / 256;   // 8

    float v[VPT];
    float mx = -3.402823466e38f;
    #pragma unroll
    for (int i = 0; i < VPT; ++i) {
        v[i] = out[(size_t)(t + i * 256) * B_SZ + b];
        mx = fmaxf(mx, v[i]);
    }

    __shared__ float sm[8];
    #pragma unroll
    for (int off = 16; off > 0; off >>= 1)
        mx = fmaxf(mx, __shfl_xor_sync(0xFFFFFFFF, mx, off));
    const int warp = t >> 5, lane = t & 31;
    if (lane == 0) sm[warp] = mx;
    __syncthreads();
    if (warp == 0) {
        float m = (lane < 8) ? sm[lane] : -3.402823466e38f;
        #pragma unroll
        for (int off = 4; off > 0; off >>= 1)
            m = fmaxf(m, __shfl_xor_sync(0xFFFFFFFF, m, off));
        if (lane == 0) sm[0] = m;
    }
    __syncthreads();
    mx = sm[0];
    __syncthreads();

    float sum = 0.f;
    #pragma unroll
    for (int i = 0; i < VPT; ++i) {
        v[i] = __expf(v[i] - mx);
        sum += v[i];
    }
    #pragma unroll
    for (int off = 16; off > 0; off >>= 1)
        sum += __shfl_xor_sync(0xFFFFFFFF, sum, off);
    if (lane == 0) sm[warp] = sum;
    __syncthreads();
    if (warp == 0) {
        float s = (lane < 8) ? sm[lane] : 0.f;
        #pragma unroll
        for (int off = 4; off > 0; off >>= 1)
            s += __shfl_xor_sync(0xFFFFFFFF, s, off);
        if (lane == 0) sm[0] = s;
    }
    __syncthreads();
    const float inv = 1.0f / sm[0];

    #pragma unroll
    for (int i = 0; i < VPT; ++i)
        out[(size_t)(t + i * 256) * B_SZ + b] = v[i] * inv;
}

// ---------------------------------------------------------------------------
extern "C" void kernel_launch(void* const* d_in, const int* in_sizes, int n_in,
                              void* d_out, int out_size)
{
    const float* enc  = (const float*)d_in[0];  // [S,B,H]
    const float* lds  = (const float*)d_in[1];  // [2,1,B,H]
    const float* W    = (const float*)d_in[2];  // [H,H]
    const float* bias = (const float*)d_in[3];  // [H]
    float* out = (float*)d_out;                 // [1,1,S,B] == [S,B]

    energy_kernel<<<256, 128>>>(lds, W, bias);
    score_kernel<<<(S_LEN / VPS) * B_SZ, 128>>>(enc, out);
    softmax_kernel<<<B_SZ, 256>>>(out);
}

// round 5
// speedup vs baseline: 1.0504x; 1.0504x over previous
#include <cuda_runtime.h>
#include <cuda_bf16.h>

#define S_LEN 2048
#define B_SZ  16
#define H_DIM 1024

__device__ float g_energy[B_SZ * H_DIM];

// ---------------------------------------------------------------------------
// Kernel 0: init g_energy[b][h] = bias[h]  (REDG partials accumulate on top)
// ---------------------------------------------------------------------------
__global__ void init_kernel(const float* __restrict__ bias)
{
    const int idx = blockIdx.x * 256 + threadIdx.x;   // 0 .. 16383
    g_energy[idx] = bias[idx & (H_DIM - 1)];
}

// ---------------------------------------------------------------------------
// Kernel 1 v5: energy partials.
// Block = 128 thr (4 warps) handles (4 h-rows) x (one 256-float j-chunk).
// State chunk [16 b][256 j] staged once in 16KB smem; W read once from DRAM.
// Each warp: 2 W LDG.128, 32 conflict-free LDS.128, 128 FFMA,
// then a value-halving butterfly (16 shfl for 16 accumulators) and 8
// predicated float atomicAdds into g_energy.
// grid = 256 row-groups * 4 chunks = 1024 blocks.
// ---------------------------------------------------------------------------
__global__ void __launch_bounds__(128)
energy_kernel(const float* __restrict__ lds,
              const float* __restrict__ W)
{
    __shared__ float4 s_st[16 * 64];     // [b][64 float4] for this chunk

    const int t    = threadIdx.x;
    const int warp = t >> 5;
    const int lane = t & 31;
    const int rg   = blockIdx.x >> 2;    // row group (4 rows)
    const int ch   = blockIdx.x & 3;     // j-chunk (256 floats = 64 float4)
    const int row  = rg * 4 + warp;      // h

    const float4* st4 = reinterpret_cast<const float4*>(lds);  // [B][256]
    const float4* W4  = reinterpret_cast<const float4*>(W);    // [H][256]

    // Stage state chunk: 1024 float4, 128 threads -> 8 each (coalesced per b-row).
    #pragma unroll
    for (int i = 0; i < 8; ++i) {
        const int v = t + i * 128;       // 0..1023
        const int b = v >> 6;
        const int k = v & 63;
        s_st[v] = st4[b * 256 + ch * 64 + k];
    }
    __syncthreads();

    // Accumulate: a[b] = sum over this warp's j range of W[row][j]*state[b][j]
    float a[16];
    #pragma unroll
    for (int b = 0; b < 16; ++b) a[b] = 0.f;

    #pragma unroll
    for (int u = 0; u < 2; ++u) {
        const int idx = u * 32 + lane;                     // float4 within chunk
        const float4 w = W4[(size_t)row * 256 + ch * 64 + idx];
        #pragma unroll
        for (int b = 0; b < 16; ++b) {
            const float4 s = s_st[b * 64 + idx];
            a[b] += w.x * s.x + w.y * s.y + w.z * s.z + w.w * s.w;
        }
    }

    // Value-halving butterfly: 16 accumulators over 32 lanes in 16 shfl.
    // After steps s=16,8,4,2 lane l tracks b = (l>>1)&15 summed over its
    // bit0-parity lane set; final xor-1 merges parities.
    int n = 16;
    #pragma unroll
    for (int s = 16; s >= 2; s >>= 1) {
        const int  half = n >> 1;
        const bool up   = (lane & s) != 0;
        #pragma unroll
        for (int i = 0; i < half; ++i) {
            const float send = up ? a[i] : a[i + half];
            const float keep = up ? a[i + half] : a[i];
            a[i] = keep + __shfl_xor_sync(0xFFFFFFFF, send, s);
        }
        n = half;
    }
    a[0] += __shfl_xor_sync(0xFFFFFFFF, a[0], 1);

    if ((lane & 1) == 0) {
        const int b = (lane >> 1) & 15;
        atomicAdd(&g_energy[(size_t)b * H_DIM + row], a[0]);
    }
}

// ---------------------------------------------------------------------------
// Kernel 2: scores[s][b] = sum_h enc[s][b][h] * energy[b][h]
// One block per (b, 8-row s-chunk): energy row in registers, reused 8x.
// ---------------------------------------------------------------------------
#define VPS 8
__global__ void __launch_bounds__(128, 8)
score_kernel(const float* __restrict__ enc, float* __restrict__ out)
{
    const int b  = blockIdx.x & (B_SZ - 1);
    const int s0 = (blockIdx.x >> 4) * VPS;
    const int t  = threadIdx.x;

    const float4* e4 = reinterpret_cast<const float4*>(enc);
    const float4* g4 = reinterpret_cast<const float4*>(g_energy);

    const float4 g0 = g4[b * (H_DIM / 4) + t];
    const float4 g1 = g4[b * (H_DIM / 4) + 128 + t];

    float acc[VPS];
    #pragma unroll
    for (int i = 0; i < VPS; ++i) {
        const size_t row = ((size_t)(s0 + i) * B_SZ + b) * (H_DIM / 4);
        const float4 a0 = e4[row + t];
        const float4 a1 = e4[row + 128 + t];
        acc[i] = a0.x * g0.x + a0.y * g0.y + a0.z * g0.z + a0.w * g0.w
               + a1.x * g1.x + a1.y * g1.y + a1.z * g1.z + a1.w * g1.w;
    }

    #pragma unroll
    for (int i = 0; i < VPS; ++i)
        #pragma unroll
        for (int off = 16; off > 0; off >>= 1)
            acc[i] += __shfl_xor_sync(0xFFFFFFFF, acc[i], off);

    __shared__ float red[4][VPS];
    const int warp = t >> 5;
    const int lane = t & 31;
    if (lane == 0) {
        #pragma unroll
        for (int i = 0; i < VPS; ++i)
            red[warp][i] = acc[i];
    }
    __syncthreads();
    if (t < VPS)
        out[(size_t)(s0 + t) * B_SZ + b] =
            red[0][t] + red[1][t] + red[2][t] + red[3][t];
}

// ---------------------------------------------------------------------------
// Kernel 3: softmax over S per batch column b, in place on d_out.
// ---------------------------------------------------------------------------
__global__ void softmax_kernel(float* __restrict__ out)
{
    const int b = blockIdx.x;
    const int t = threadIdx.x;
    const int VPT = S_LEN / 256;   // 8

    float v[VPT];
    float mx = -3.402823466e38f;
    #pragma unroll
    for (int i = 0; i < VPT; ++i) {
        v[i] = out[(size_t)(t + i * 256) * B_SZ + b];
        mx = fmaxf(mx, v[i]);
    }

    __shared__ float sm[8];
    #pragma unroll
    for (int off = 16; off > 0; off >>= 1)
        mx = fmaxf(mx, __shfl_xor_sync(0xFFFFFFFF, mx, off));
    const int warp = t >> 5, lane = t & 31;
    if (lane == 0) sm[warp] = mx;
    __syncthreads();
    if (warp == 0) {
        float m = (lane < 8) ? sm[lane] : -3.402823466e38f;
        #pragma unroll
        for (int off = 4; off > 0; off >>= 1)
            m = fmaxf(m, __shfl_xor_sync(0xFFFFFFFF, m, off));
        if (lane == 0) sm[0] = m;
    }
    __syncthreads();
    mx = sm[0];
    __syncthreads();

    float sum = 0.f;
    #pragma unroll
    for (int i = 0; i < VPT; ++i) {
        v[i] = __expf(v[i] - mx);
        sum += v[i];
    }
    #pragma unroll
    for (int off = 16; off > 0; off >>= 1)
        sum += __shfl_xor_sync(0xFFFFFFFF, sum, off);
    if (lane == 0) sm[warp] = sum;
    __syncthreads();
    if (warp == 0) {
        float s = (lane < 8) ? sm[lane] : 0.f;
        #pragma unroll
        for (int off = 4; off > 0; off >>= 1)
            s += __shfl_xor_sync(0xFFFFFFFF, s, off);
        if (lane == 0) sm[0] = s;
    }
    __syncthreads();
    const float inv = 1.0f / sm[0];

    #pragma unroll
    for (int i = 0; i < VPT; ++i)
        out[(size_t)(t + i * 256) * B_SZ + b] = v[i] * inv;
}

// ---------------------------------------------------------------------------
extern "C" void kernel_launch(void* const* d_in, const int* in_sizes, int n_in,
                              void* d_out, int out_size)
{
    const float* enc  = (const float*)d_in[0];  // [S,B,H]
    const float* lds  = (const float*)d_in[1];  // [2,1,B,H]
    const float* W    = (const float*)d_in[2];  // [H,H]
    const float* bias = (const float*)d_in[3];  // [H]
    float* out = (float*)d_out;                 // [1,1,S,B] == [S,B]

    init_kernel<<<B_SZ * H_DIM / 256, 256>>>(bias);
    energy_kernel<<<1024, 128>>>(lds, W);
    score_kernel<<<(S_LEN / VPS) * B_SZ, 128>>>(enc, out);
    softmax_kernel<<<B_SZ, 256>>>(out);
}

// round 6
// speedup vs baseline: 1.0725x; 1.0211x over previous
#include <cuda_runtime.h>
#include <cuda_bf16.h>

#define S_LEN 2048
#define B_SZ  16
#define H_DIM 1024

// 4 chunk-partial slabs: g_part[ch][b][h]  (race-free -> no init kernel)
__device__ float g_part[4][B_SZ * H_DIM];

// ---------------------------------------------------------------------------
// Kernel 1: energy partials.
// Block = 128 thr (4 warps) handles (4 h-rows) x (one 256-float j-chunk).
// State chunk [16 b][256 j] staged in 16KB smem; W read once from DRAM.
// Each warp: 2 W LDG.128, 32 conflict-free LDS.128, 128 FFMA, 16-shfl
// value-halving butterfly, then 16 plain stores into its own slab.
// grid = 256 row-groups * 4 chunks = 1024 blocks.
// ---------------------------------------------------------------------------
__global__ void __launch_bounds__(128)
energy_kernel(const float* __restrict__ lds,
              const float* __restrict__ W)
{
    __shared__ float4 s_st[16 * 64];     // [b][64 float4] for this chunk

    const int t    = threadIdx.x;
    const int warp = t >> 5;
    const int lane = t & 31;
    const int rg   = blockIdx.x >> 2;    // row group (4 rows)
    const int ch   = blockIdx.x & 3;     // j-chunk (256 floats = 64 float4)
    const int row  = rg * 4 + warp;      // h

    const float4* st4 = reinterpret_cast<const float4*>(lds);  // [B][256]
    const float4* W4  = reinterpret_cast<const float4*>(W);    // [H][256]

    #pragma unroll
    for (int i = 0; i < 8; ++i) {
        const int v = t + i * 128;       // 0..1023
        const int b = v >> 6;
        const int k = v & 63;
        s_st[v] = st4[b * 256 + ch * 64 + k];
    }
    __syncthreads();

    float a[16];
    #pragma unroll
    for (int b = 0; b < 16; ++b) a[b] = 0.f;

    #pragma unroll
    for (int u = 0; u < 2; ++u) {
        const int idx = u * 32 + lane;
        const float4 w = W4[(size_t)row * 256 + ch * 64 + idx];
        #pragma unroll
        for (int b = 0; b < 16; ++b) {
            const float4 s = s_st[b * 64 + idx];
            a[b] += w.x * s.x + w.y * s.y + w.z * s.z + w.w * s.w;
        }
    }

    // Value-halving butterfly: 16 accumulators over 32 lanes in 16 shfl.
    int n = 16;
    #pragma unroll
    for (int s = 16; s >= 2; s >>= 1) {
        const int  half = n >> 1;
        const bool up   = (lane & s) != 0;
        #pragma unroll
        for (int i = 0; i < half; ++i) {
            const float send = up ? a[i] : a[i + half];
            const float keep = up ? a[i + half] : a[i];
            a[i] = keep + __shfl_xor_sync(0xFFFFFFFF, send, s);
        }
        n = half;
    }
    a[0] += __shfl_xor_sync(0xFFFFFFFF, a[0], 1);

    if ((lane & 1) == 0) {
        const int b = (lane >> 1) & 15;
        g_part[ch][(size_t)b * H_DIM + row] = a[0];
    }
}

// ---------------------------------------------------------------------------
// Kernel 2: scores[s][b] = sum_h enc[s][b][h] * energy[b][h]
// energy row reconstructed as sum of 4 partial slabs + bias (L2-resident).
// One block per (b, 8-row s-chunk): energy row in registers, reused 8x.
// ---------------------------------------------------------------------------
#define VPS 8
__global__ void __launch_bounds__(128, 8)
score_kernel(const float* __restrict__ enc,
             const float* __restrict__ bias,
             float* __restrict__ out)
{
    const int b  = blockIdx.x & (B_SZ - 1);
    const int s0 = (blockIdx.x >> 4) * VPS;
    const int t  = threadIdx.x;

    const float4* e4 = reinterpret_cast<const float4*>(enc);
    const float4* b4 = reinterpret_cast<const float4*>(bias);

    float4 g0, g1;
    {
        const float4 bb0 = b4[t];
        const float4 bb1 = b4[128 + t];
        g0 = bb0; g1 = bb1;
        #pragma unroll
        for (int c = 0; c < 4; ++c) {
            const float4* p4 = reinterpret_cast<const float4*>(g_part[c]);
            const float4 p0 = p4[b * (H_DIM / 4) + t];
            const float4 p1 = p4[b * (H_DIM / 4) + 128 + t];
            g0.x += p0.x; g0.y += p0.y; g0.z += p0.z; g0.w += p0.w;
            g1.x += p1.x; g1.y += p1.y; g1.z += p1.z; g1.w += p1.w;
        }
    }

    float acc[VPS];
    #pragma unroll
    for (int i = 0; i < VPS; ++i) {
        const size_t row = ((size_t)(s0 + i) * B_SZ + b) * (H_DIM / 4);
        const float4 a0 = e4[row + t];
        const float4 a1 = e4[row + 128 + t];
        acc[i] = a0.x * g0.x + a0.y * g0.y + a0.z * g0.z + a0.w * g0.w
               + a1.x * g1.x + a1.y * g1.y + a1.z * g1.z + a1.w * g1.w;
    }

    #pragma unroll
    for (int i = 0; i < VPS; ++i)
        #pragma unroll
        for (int off = 16; off > 0; off >>= 1)
            acc[i] += __shfl_xor_sync(0xFFFFFFFF, acc[i], off);

    __shared__ float red[4][VPS];
    const int warp = t >> 5;
    const int lane = t & 31;
    if (lane == 0) {
        #pragma unroll
        for (int i = 0; i < VPS; ++i)
            red[warp][i] = acc[i];
    }
    __syncthreads();
    if (t < VPS)
        out[(size_t)(s0 + t) * B_SZ + b] =
            red[0][t] + red[1][t] + red[2][t] + red[3][t];
}

// ---------------------------------------------------------------------------
// Kernel 3 v2: softmax over S per column b.
// 16 blocks x 1024 threads, 2 values/thread in registers, two block-wide
// reductions (warp shuffle + 32-entry smem). One pass over data.
// ---------------------------------------------------------------------------
__global__ void __launch_bounds__(1024)
softmax_kernel(float* __restrict__ out)
{
    const int b = blockIdx.x;
    const int t = threadIdx.x;

    float v0 = out[(size_t)t * B_SZ + b];
    float v1 = out[(size_t)(t + 1024) * B_SZ + b];

    __shared__ float sm[32];
    const int warp = t >> 5, lane = t & 31;

    // ---- block max ----
    float mx = fmaxf(v0, v1);
    #pragma unroll
    for (int off = 16; off > 0; off >>= 1)
        mx = fmaxf(mx, __shfl_xor_sync(0xFFFFFFFF, mx, off));
    if (lane == 0) sm[warp] = mx;
    __syncthreads();
    if (warp == 0) {
        float m = sm[lane];
        #pragma unroll
        for (int off = 16; off > 0; off >>= 1)
            m = fmaxf(m, __shfl_xor_sync(0xFFFFFFFF, m, off));
        if (lane == 0) sm[0] = m;
    }
    __syncthreads();
    mx = sm[0];
    __syncthreads();

    // ---- exp + block sum ----
    v0 = __expf(v0 - mx);
    v1 = __expf(v1 - mx);
    float sum = v0 + v1;
    #pragma unroll
    for (int off = 16; off > 0; off >>= 1)
        sum += __shfl_xor_sync(0xFFFFFFFF, sum, off);
    if (lane == 0) sm[warp] = sum;
    __syncthreads();
    if (warp == 0) {
        float s = sm[lane];
        #pragma unroll
        for (int off = 16; off > 0; off >>= 1)
            s += __shfl_xor_sync(0xFFFFFFFF, s, off);
        if (lane == 0) sm[0] = s;
    }
    __syncthreads();
    const float inv = 1.0f / sm[0];

    out[(size_t)t * B_SZ + b]          = v0 * inv;
    out[(size_t)(t + 1024) * B_SZ + b] = v1 * inv;
}

// ---------------------------------------------------------------------------
extern "C" void kernel_launch(void* const* d_in, const int* in_sizes, int n_in,
                              void* d_out, int out_size)
{
    const float* enc  = (const float*)d_in[0];  // [S,B,H]
    const float* lds  = (const float*)d_in[1];  // [2,1,B,H]
    const float* W    = (const float*)d_in[2];  // [H,H]
    const float* bias = (const float*)d_in[3];  // [H]
    float* out = (float*)d_out;                 // [1,1,S,B] == [S,B]

    energy_kernel<<<1024, 128>>>(lds, W);
    score_kernel<<<(S_LEN / VPS) * B_SZ, 128>>>(enc, bias, out);
    softmax_kernel<<<B_SZ, 1024>>>(out);
}

// round 7
// speedup vs baseline: 1.1242x; 1.0481x over previous
#include <cuda_runtime.h>
#include <cuda_bf16.h>

#define S_LEN 2048
#define B_SZ  16
#define H_DIM 1024

// 4 chunk-partial slabs: g_part[ch][b][h]  (race-free -> no init kernel)
__device__ float g_part[4][B_SZ * H_DIM];

// ---------------------------------------------------------------------------
// Kernel 1 v7: energy partials.
// Block = 128 thr (4 warps); block covers (8 h-rows) x (one 256-float chunk).
// Warp owns 2 rows: 4 W LDG.128, 32 LDS.128 each feeding 8 FFMAs,
// 32 accumulators (2 rows x 16 b) -> full 32-value butterfly (31 shfl),
// all 32 lanes store one partial. grid = 128 rowgroups * 4 chunks = 512.
// ---------------------------------------------------------------------------
__global__ void __launch_bounds__(128)
energy_kernel(const float* __restrict__ lds,
              const float* __restrict__ W)
{
    __shared__ float4 s_st[16 * 64];     // [b][64 float4] for this chunk

    const int t    = threadIdx.x;
    const int warp = t >> 5;
    const int lane = t & 31;
    const int rg   = blockIdx.x >> 2;    // 8-row group
    const int ch   = blockIdx.x & 3;     // j-chunk (256 floats = 64 float4)
    const int row0 = rg * 8 + warp * 2;  // first of this warp's 2 rows

    const float4* st4 = reinterpret_cast<const float4*>(lds);  // [B][256]
    const float4* W4  = reinterpret_cast<const float4*>(W);    // [H][256]

    // Stage state chunk: 1024 float4, 128 threads -> 8 each.
    #pragma unroll
    for (int i = 0; i < 8; ++i) {
        const int v = t + i * 128;       // 0..1023
        const int b = v >> 6;
        const int k = v & 63;
        s_st[v] = st4[b * 256 + ch * 64 + k];
    }
    __syncthreads();

    float a[32];                          // a[r*16+b]
    #pragma unroll
    for (int v = 0; v < 32; ++v) a[v] = 0.f;

    #pragma unroll
    for (int u = 0; u < 2; ++u) {
        const int idx = u * 32 + lane;
        const float4 w0 = W4[(size_t)row0 * 256 + ch * 64 + idx];
        const float4 w1 = W4[(size_t)(row0 + 1) * 256 + ch * 64 + idx];
        #pragma unroll
        for (int b = 0; b < 16; ++b) {
            const float4 s = s_st[b * 64 + idx];
            a[b]      += w0.x * s.x + w0.y * s.y + w0.z * s.z + w0.w * s.w;
            a[16 + b] += w1.x * s.x + w1.y * s.y + w1.z * s.z + w1.w * s.w;
        }
    }

    // Value-halving butterfly over 32 accumulators:
    // after all steps, lane l holds the warp-total of original a[l].
    int n = 32;
    #pragma unroll
    for (int s = 16; s >= 1; s >>= 1) {
        const int  half = n >> 1;
        const bool up   = (lane & s) != 0;
        #pragma unroll
        for (int i = 0; i < half; ++i) {
            const float send = up ? a[i] : a[i + half];
            const float keep = up ? a[i + half] : a[i];
            a[i] = keep + __shfl_xor_sync(0xFFFFFFFF, send, s);
        }
        n = half;
    }

    // lane l -> (r = l>>4, b = l&15)
    const int r = lane >> 4;
    const int b = lane & 15;
    g_part[ch][(size_t)b * H_DIM + row0 + r] = a[0];
}

// ---------------------------------------------------------------------------
// Kernel 2: scores[s][b] = sum_h enc[s][b][h] * energy[b][h]
// energy row reconstructed as sum of 4 partial slabs + bias (L2-resident).
// One block per (b, 8-row s-chunk): energy row in registers, reused 8x.
// ---------------------------------------------------------------------------
#define VPS 8
__global__ void __launch_bounds__(128, 8)
score_kernel(const float* __restrict__ enc,
             const float* __restrict__ bias,
             float* __restrict__ out)
{
    const int b  = blockIdx.x & (B_SZ - 1);
    const int s0 = (blockIdx.x >> 4) * VPS;
    const int t  = threadIdx.x;

    const float4* e4 = reinterpret_cast<const float4*>(enc);
    const float4* b4 = reinterpret_cast<const float4*>(bias);

    float4 g0 = b4[t];
    float4 g1 = b4[128 + t];
    #pragma unroll
    for (int c = 0; c < 4; ++c) {
        const float4* p4 = reinterpret_cast<const float4*>(g_part[c]);
        const float4 p0 = p4[b * (H_DIM / 4) + t];
        const float4 p1 = p4[b * (H_DIM / 4) + 128 + t];
        g0.x += p0.x; g0.y += p0.y; g0.z += p0.z; g0.w += p0.w;
        g1.x += p1.x; g1.y += p1.y; g1.z += p1.z; g1.w += p1.w;
    }

    float acc[VPS];
    #pragma unroll
    for (int i = 0; i < VPS; ++i) {
        const size_t row = ((size_t)(s0 + i) * B_SZ + b) * (H_DIM / 4);
        const float4 a0 = e4[row + t];
        const float4 a1 = e4[row + 128 + t];
        acc[i] = a0.x * g0.x + a0.y * g0.y + a0.z * g0.z + a0.w * g0.w
               + a1.x * g1.x + a1.y * g1.y + a1.z * g1.z + a1.w * g1.w;
    }

    #pragma unroll
    for (int i = 0; i < VPS; ++i)
        #pragma unroll
        for (int off = 16; off > 0; off >>= 1)
            acc[i] += __shfl_xor_sync(0xFFFFFFFF, acc[i], off);

    __shared__ float red[4][VPS];
    const int warp = t >> 5;
    const int lane = t & 31;
    if (lane == 0) {
        #pragma unroll
        for (int i = 0; i < VPS; ++i)
            red[warp][i] = acc[i];
    }
    __syncthreads();
    if (t < VPS)
        out[(size_t)(s0 + t) * B_SZ + b] =
            red[0][t] + red[1][t] + red[2][t] + red[3][t];
}

// ---------------------------------------------------------------------------
// Kernel 3: softmax over S per column b. 16 blocks x 1024 threads,
// 2 values/thread in registers, two block-wide reductions.
// ---------------------------------------------------------------------------
__global__ void __launch_bounds__(1024)
softmax_kernel(float* __restrict__ out)
{
    const int b = blockIdx.x;
    const int t = threadIdx.x;

    float v0 = out[(size_t)t * B_SZ + b];
    float v1 = out[(size_t)(t + 1024) * B_SZ + b];

    __shared__ float sm[32];
    const int warp = t >> 5, lane = t & 31;

    float mx = fmaxf(v0, v1);
    #pragma unroll
    for (int off = 16; off > 0; off >>= 1)
        mx = fmaxf(mx, __shfl_xor_sync(0xFFFFFFFF, mx, off));
    if (lane == 0) sm[warp] = mx;
    __syncthreads();
    if (warp == 0) {
        float m = sm[lane];
        #pragma unroll
        for (int off = 16; off > 0; off >>= 1)
            m = fmaxf(m, __shfl_xor_sync(0xFFFFFFFF, m, off));
        if (lane == 0) sm[0] = m;
    }
    __syncthreads();
    mx = sm[0];
    __syncthreads();

    v0 = __expf(v0 - mx);
    v1 = __expf(v1 - mx);
    float sum = v0 + v1;
    #pragma unroll
    for (int off = 16; off > 0; off >>= 1)
        sum += __shfl_xor_sync(0xFFFFFFFF, sum, off);
    if (lane == 0) sm[warp] = sum;
    __syncthreads();
    if (warp == 0) {
        float s = sm[lane];
        #pragma unroll
        for (int off = 16; off > 0; off >>= 1)
            s += __shfl_xor_sync(0xFFFFFFFF, s, off);
        if (lane == 0) sm[0] = s;
    }
    __syncthreads();
    const float inv = 1.0f / sm[0];

    out[(size_t)t * B_SZ + b]          = v0 * inv;
    out[(size_t)(t + 1024) * B_SZ + b] = v1 * inv;
}

// ---------------------------------------------------------------------------
extern "C" void kernel_launch(void* const* d_in, const int* in_sizes, int n_in,
                              void* d_out, int out_size)
{
    const float* enc  = (const float*)d_in[0];  // [S,B,H]
    const float* lds  = (const float*)d_in[1];  // [2,1,B,H]
    const float* W    = (const float*)d_in[2];  // [H,H]
    const float* bias = (const float*)d_in[3];  // [H]
    float* out = (float*)d_out;                 // [1,1,S,B] == [S,B]

    energy_kernel<<<512, 128>>>(lds, W);
    score_kernel<<<(S_LEN / VPS) * B_SZ, 128>>>(enc, bias, out);
    softmax_kernel<<<B_SZ, 1024>>>(out);
}